// round 1
// baseline (speedup 1.0000x reference)
#include <cuda_runtime.h>

#define S_LEN 2048
#define HEADS 8
#define BATCH 2
#define DHEAD 128
#define BM 64
#define BN 64

// smem layout (floats)
#define QS_OFF 0
#define KS_OFF (BM * DHEAD)
#define VS_STRIDE 132
#define VS_OFF (KS_OFF + BN * DHEAD)
#define SS_STRIDE 68
#define SS_OFF (VS_OFF + BN * VS_STRIDE)
#define SMEM_FLOATS (SS_OFF + BM * SS_STRIDE)
#define SMEM_BYTES (SMEM_FLOATS * 4)

__device__ float g_rnorm[HEADS * S_LEN];

__device__ __forceinline__ void fma2(unsigned long long& d, unsigned long long a,
                                     unsigned long long b) {
    asm("fma.rn.f32x2 %0, %1, %2, %0;" : "+l"(d) : "l"(a), "l"(b));
}
__device__ __forceinline__ float2 upk(unsigned long long a) {
    float2 f;
    asm("mov.b64 {%0, %1}, %2;" : "=f"(f.x), "=f"(f.y) : "l"(a));
    return f;
}
__device__ __forceinline__ unsigned long long dupf(float v) {
    unsigned long long r;
    asm("mov.b64 %0, {%1, %1};" : "=l"(r) : "f"(v));
    return r;
}

// ---------------- rnorm: rnorm[h,i] = rsqrt(sum_j omask[h,i,j]) ----------------
__global__ void rnorm_kernel(const float* __restrict__ omask) {
    int row = blockIdx.x;  // h*S + i
    const float* p = omask + (size_t)row * S_LEN;
    float s = 0.f;
    for (int j = threadIdx.x * 4; j < S_LEN; j += 256 * 4) {
        float4 f = *(const float4*)(p + j);
        s += f.x + f.y + f.z + f.w;
    }
#pragma unroll
    for (int off = 16; off > 0; off >>= 1) s += __shfl_xor_sync(0xffffffffu, s, off);
    __shared__ float red[8];
    if ((threadIdx.x & 31) == 0) red[threadIdx.x >> 5] = s;
    __syncthreads();
    if (threadIdx.x == 0) {
        float t = 0.f;
#pragma unroll
        for (int i = 0; i < 8; i++) t += red[i];
        g_rnorm[row] = (t > 0.f) ? rsqrtf(t) : 0.f;  // nan_to_num guard
    }
}

// ---------------- fused retention ----------------
__global__ __launch_bounds__(256, 1)
void retention_kernel(const float* __restrict__ q, const float* __restrict__ k,
                      const float* __restrict__ v, const float* __restrict__ omask,
                      float* __restrict__ out) {
    extern __shared__ float sm[];
    float* Qs = sm + QS_OFF;
    float* Ks = sm + KS_OFF;
    float* Vs = sm + VS_OFF;
    float* Ss = sm + SS_OFF;

    const int it = blockIdx.x, h = blockIdx.y, b = blockIdx.z;
    const int tid = threadIdx.x;
    const int ty = tid >> 4, tx = tid & 15;
    const int i0 = it * BM;

    const size_t bh = (size_t)(b * HEADS + h);
    const float* qbase = q + (bh * S_LEN + i0) * DHEAD;
    const float* kbase = k + bh * S_LEN * DHEAD;
    const float* vbase = v + bh * S_LEN * DHEAD;
    const float* mbase = omask + ((size_t)h * S_LEN + i0) * S_LEN;

    // load Q tile (swizzled on row>>2 so GEMM1 K-side lanes are conflict-free)
    for (int x = tid; x < BM * (DHEAD / 4); x += 256) {
        int row = x >> 5, c4 = (x & 31) << 2;
        float4 f = *(const float4*)(qbase + row * DHEAD + c4);
        *(float4*)(Qs + row * DHEAD + (c4 ^ (((row >> 2) & 7) << 2))) = f;
    }

    float rn[4];
#pragma unroll
    for (int r = 0; r < 4; r++) rn[r] = g_rnorm[h * S_LEN + i0 + ty * 4 + r];

    const int qswz = (ty & 7) << 2;  // ((ty*4+r)>>2)&7 == ty&7 for r<4
    const int kswz = (tx & 7) << 2;

    unsigned long long oacc[4][4];
#pragma unroll
    for (int r = 0; r < 4; r++)
#pragma unroll
        for (int c = 0; c < 4; c++) oacc[r][c] = 0ull;

    for (int jt = 0; jt < S_LEN / BN; jt++) {
        __syncthreads();  // prev GEMM2 done with Vs/Ss
        const float* kb_ = kbase + (size_t)(jt * BN) * DHEAD;
        const float* vb_ = vbase + (size_t)(jt * BN) * DHEAD;
        for (int x = tid; x < BN * (DHEAD / 4); x += 256) {
            int row = x >> 5, c4 = (x & 31) << 2;
            float4 fk = *(const float4*)(kb_ + row * DHEAD + c4);
            *(float4*)(Ks + row * DHEAD + (c4 ^ (((row >> 2) & 7) << 2))) = fk;
            float4 fv = *(const float4*)(vb_ + row * DHEAD + c4);
            *(float4*)(Vs + row * VS_STRIDE + c4) = fv;
        }
        __syncthreads();

        // ---- GEMM1: S[64,64] = Q @ K^T, f32x2 packed along reduction k ----
        unsigned long long sacc[4][4];
#pragma unroll
        for (int r = 0; r < 4; r++)
#pragma unroll
            for (int c = 0; c < 4; c++) sacc[r][c] = 0ull;

#pragma unroll 4
        for (int k0 = 0; k0 < DHEAD; k0 += 4) {
            int qc = k0 ^ qswz;
            int kc = k0 ^ kswz;
            ulonglong2 qa[4], kb2[4];
#pragma unroll
            for (int r = 0; r < 4; r++)
                qa[r] = *(const ulonglong2*)(Qs + (ty * 4 + r) * DHEAD + qc);
#pragma unroll
            for (int c = 0; c < 4; c++)
                kb2[c] = *(const ulonglong2*)(Ks + (tx * 4 + c) * DHEAD + kc);
#pragma unroll
            for (int r = 0; r < 4; r++)
#pragma unroll
                for (int c = 0; c < 4; c++) {
                    fma2(sacc[r][c], qa[r].x, kb2[c].x);
                    fma2(sacc[r][c], qa[r].y, kb2[c].y);
                }
        }

        // ---- mask * rnorm, write S tile to smem ----
#pragma unroll
        for (int r = 0; r < 4; r++) {
            const float* mp = mbase + (size_t)(ty * 4 + r) * S_LEN + jt * BN + tx * 4;
            float4 m = *(const float4*)mp;
            float2 p0 = upk(sacc[r][0]), p1 = upk(sacc[r][1]);
            float2 p2 = upk(sacc[r][2]), p3 = upk(sacc[r][3]);
            float4 sv;
            sv.x = (p0.x + p0.y) * m.x * rn[r];
            sv.y = (p1.x + p1.y) * m.y * rn[r];
            sv.z = (p2.x + p2.y) * m.z * rn[r];
            sv.w = (p3.x + p3.y) * m.w * rn[r];
            *(float4*)(Ss + (ty * 4 + r) * SS_STRIDE + tx * 4) = sv;
        }
        __syncthreads();

        // ---- GEMM2: O += S @ V, f32x2 packed along output d ----
#pragma unroll 2
        for (int j0 = 0; j0 < BN; j0 += 4) {
            float4 sr[4];
#pragma unroll
            for (int r = 0; r < 4; r++)
                sr[r] = *(const float4*)(Ss + (ty * 4 + r) * SS_STRIDE + j0);
            ulonglong2 va[4], vb2[4];
#pragma unroll
            for (int jj = 0; jj < 4; jj++) {
                const float* vp = Vs + (j0 + jj) * VS_STRIDE;
                va[jj] = *(const ulonglong2*)(vp + tx * 4);
                vb2[jj] = *(const ulonglong2*)(vp + 64 + tx * 4);
            }
#pragma unroll
            for (int r = 0; r < 4; r++) {
                const float* srf = (const float*)&sr[r];
#pragma unroll
                for (int jj = 0; jj < 4; jj++) {
                    unsigned long long sd = dupf(srf[jj]);
                    fma2(oacc[r][0], sd, va[jj].x);
                    fma2(oacc[r][1], sd, va[jj].y);
                    fma2(oacc[r][2], sd, vb2[jj].x);
                    fma2(oacc[r][3], sd, vb2[jj].y);
                }
            }
        }
    }

    // ---- RMSNorm over D2=128 and store ----
    float* obase = out + (bh * S_LEN + i0) * DHEAD;
#pragma unroll
    for (int r = 0; r < 4; r++) {
        float2 a0 = upk(oacc[r][0]), a1 = upk(oacc[r][1]);
        float2 a2 = upk(oacc[r][2]), a3 = upk(oacc[r][3]);
        float ss = a0.x * a0.x + a0.y * a0.y + a1.x * a1.x + a1.y * a1.y +
                   a2.x * a2.x + a2.y * a2.y + a3.x * a3.x + a3.y * a3.y;
#pragma unroll
        for (int off = 1; off < 16; off <<= 1) ss += __shfl_xor_sync(0xffffffffu, ss, off);
        float sc = rsqrtf(ss * (1.f / 128.f) + 1e-6f);
        float* op = obase + (size_t)(ty * 4 + r) * DHEAD;
        float4 w0 = {a0.x * sc, a0.y * sc, a1.x * sc, a1.y * sc};
        float4 w1 = {a2.x * sc, a2.y * sc, a3.x * sc, a3.y * sc};
        *(float4*)(op + tx * 4) = w0;
        *(float4*)(op + 64 + tx * 4) = w1;
    }
}

extern "C" void kernel_launch(void* const* d_in, const int* in_sizes, int n_in,
                              void* d_out, int out_size) {
    const float* q = (const float*)d_in[0];
    const float* k = (const float*)d_in[1];
    const float* v = (const float*)d_in[2];
    const float* omask = (const float*)d_in[3];
    float* out = (float*)d_out;

    cudaFuncSetAttribute(retention_kernel, cudaFuncAttributeMaxDynamicSharedMemorySize,
                         SMEM_BYTES);

    rnorm_kernel<<<HEADS * S_LEN, 256>>>(omask);
    retention_kernel<<<dim3(S_LEN / BM, HEADS, BATCH), 256, SMEM_BYTES>>>(q, k, v, omask,
                                                                          out);
}

// round 2
// speedup vs baseline: 1.0982x; 1.0982x over previous
#include <cuda_runtime.h>

#define S_LEN 2048
#define HEADS 8
#define BATCH 2
#define DHEAD 128
#define BM 64
#define BN 64
#define THREADS 128

// smem layout (floats)
#define QS_OFF 0
#define KS_OFF (64 * 128)
#define VS_OFF (2 * 64 * 128)
#define SS_STRIDE 66
#define SS_OFF (3 * 64 * 128)
#define SMEM_FLOATS (SS_OFF + 64 * SS_STRIDE)
#define SMEM_BYTES (SMEM_FLOATS * 4)

__device__ float g_rnorm[HEADS * S_LEN];

__device__ __forceinline__ void fma2(unsigned long long& d, unsigned long long a,
                                     unsigned long long b) {
    asm("fma.rn.f32x2 %0, %1, %2, %0;" : "+l"(d) : "l"(a), "l"(b));
}
__device__ __forceinline__ float2 upk(unsigned long long a) {
    float2 f;
    asm("mov.b64 {%0, %1}, %2;" : "=f"(f.x), "=f"(f.y) : "l"(a));
    return f;
}
__device__ __forceinline__ unsigned long long dupf(float v) {
    unsigned long long r;
    asm("mov.b64 %0, {%1, %1};" : "=l"(r) : "f"(v));
    return r;
}

// ---------------- rnorm: rnorm[h,i] = rsqrt(sum_j omask[h,i,j]) ----------------
__global__ void rnorm_kernel(const float* __restrict__ omask) {
    int row = blockIdx.x;  // h*S + i
    const float* p = omask + (size_t)row * S_LEN;
    float s = 0.f;
    for (int j = threadIdx.x * 4; j < S_LEN; j += 256 * 4) {
        float4 f = *(const float4*)(p + j);
        s += f.x + f.y + f.z + f.w;
    }
#pragma unroll
    for (int off = 16; off > 0; off >>= 1) s += __shfl_xor_sync(0xffffffffu, s, off);
    __shared__ float red[8];
    if ((threadIdx.x & 31) == 0) red[threadIdx.x >> 5] = s;
    __syncthreads();
    if (threadIdx.x == 0) {
        float t = 0.f;
#pragma unroll
        for (int i = 0; i < 8; i++) t += red[i];
        g_rnorm[row] = (t > 0.f) ? rsqrtf(t) : 0.f;  // nan_to_num guard
    }
}

// ---------------- fused retention ----------------
__global__ __launch_bounds__(THREADS, 2)
void retention_kernel(const float* __restrict__ q, const float* __restrict__ k,
                      const float* __restrict__ v, const float* __restrict__ omask,
                      float* __restrict__ out) {
    extern __shared__ float sm[];
    float* Qs = sm + QS_OFF;
    float* Ks = sm + KS_OFF;
    float* Vs = sm + VS_OFF;
    float* Ss = sm + SS_OFF;

    const int it = blockIdx.x, h = blockIdx.y, b = blockIdx.z;
    const int tid = threadIdx.x;
    const int ty = tid >> 4, tx = tid & 15;  // 8 x 16 threads
    const int i0 = it * BM;

    const size_t bh = (size_t)(b * HEADS + h);
    const float* qbase = q + (bh * S_LEN + i0) * DHEAD;
    const float* kbase = k + bh * S_LEN * DHEAD;
    const float* vbase = v + bh * S_LEN * DHEAD;
    const float* mbase = omask + ((size_t)h * S_LEN + i0) * S_LEN;

    // load Q tile (64x128), 8B-granular xor swizzle on row bit-3
    for (int x = tid; x < 64 * 32; x += THREADS) {
        int row = x >> 5, c4 = (x & 31) << 2;
        float4 f = *(const float4*)(qbase + row * DHEAD + c4);
        int s = ((row >> 3) & 1) << 1;
        float* p = Qs + row * 128;
        *(float2*)(p + (c4 ^ s)) = make_float2(f.x, f.y);
        *(float2*)(p + ((c4 + 2) ^ s)) = make_float2(f.z, f.w);
    }

    float rn[8];
#pragma unroll
    for (int r = 0; r < 8; r++) rn[r] = g_rnorm[h * S_LEN + i0 + ty * 8 + r];

    const int qswz = (ty & 1) << 1;
    const int kswz = tx << 1;

    unsigned long long oacc[8][4];
#pragma unroll
    for (int r = 0; r < 8; r++)
#pragma unroll
        for (int g = 0; g < 4; g++) oacc[r][g] = 0ull;

    for (int jt = 0; jt < S_LEN / BN; jt++) {
        __syncthreads();  // prev iter done with Ks/Vs/Ss
        const float* kb_ = kbase + (size_t)(jt * BN) * DHEAD;
        const float* vb_ = vbase + (size_t)(jt * BN) * DHEAD;
        for (int x = tid; x < 64 * 32; x += THREADS) {
            int row = x >> 5, c4 = (x & 31) << 2;
            float4 fk = *(const float4*)(kb_ + row * DHEAD + c4);
            int s = ((row >> 2) & 15) << 1;
            float* p = Ks + row * 128;
            *(float2*)(p + (c4 ^ s)) = make_float2(fk.x, fk.y);
            *(float2*)(p + ((c4 + 2) ^ s)) = make_float2(fk.z, fk.w);
            float4 fv = *(const float4*)(vb_ + row * DHEAD + c4);
            *(float4*)(Vs + row * 128 + c4) = fv;
        }
        __syncthreads();

        // ---- GEMM1: S[64,64] = Q @ K^T, f32x2 packed along reduction k ----
        unsigned long long sacc[8][4];
#pragma unroll
        for (int r = 0; r < 8; r++)
#pragma unroll
            for (int c = 0; c < 4; c++) sacc[r][c] = 0ull;

#pragma unroll 2
        for (int kw = 0; kw < DHEAD; kw += 2) {
            unsigned long long qa[8], kb2[4];
#pragma unroll
            for (int r = 0; r < 8; r++)
                qa[r] = *(const unsigned long long*)(Qs + (ty * 8 + r) * 128 + (kw ^ qswz));
#pragma unroll
            for (int c = 0; c < 4; c++)
                kb2[c] = *(const unsigned long long*)(Ks + (tx * 4 + c) * 128 + (kw ^ kswz));
#pragma unroll
            for (int r = 0; r < 8; r++)
#pragma unroll
                for (int c = 0; c < 4; c++) fma2(sacc[r][c], qa[r], kb2[c]);
        }

        // ---- mask * rnorm, write S tile (stride 66, 8B stores) ----
#pragma unroll
        for (int r = 0; r < 8; r++) {
            const float* mp = mbase + (size_t)(ty * 8 + r) * S_LEN + jt * BN + tx * 4;
            float4 m = *(const float4*)mp;
            float2 p0 = upk(sacc[r][0]), p1 = upk(sacc[r][1]);
            float2 p2 = upk(sacc[r][2]), p3 = upk(sacc[r][3]);
            float rnr = rn[r];
            float* sp = Ss + (ty * 8 + r) * SS_STRIDE + tx * 4;
            *(float2*)sp = make_float2((p0.x + p0.y) * m.x * rnr, (p1.x + p1.y) * m.y * rnr);
            *(float2*)(sp + 2) =
                make_float2((p2.x + p2.y) * m.z * rnr, (p3.x + p3.y) * m.w * rnr);
        }
        __syncthreads();

        // ---- GEMM2: O += S @ V, f32x2 packed along output d ----
#pragma unroll 2
        for (int j0 = 0; j0 < BN; j0 += 2) {
            unsigned long long sp[8];
#pragma unroll
            for (int r = 0; r < 8; r++)
                sp[r] = *(const unsigned long long*)(Ss + (ty * 8 + r) * SS_STRIDE + j0);
            unsigned long long v0[4], v1[4];
#pragma unroll
            for (int g = 0; g < 4; g++) {
                v0[g] = *(const unsigned long long*)(Vs + j0 * 128 + g * 32 + tx * 2);
                v1[g] = *(const unsigned long long*)(Vs + (j0 + 1) * 128 + g * 32 + tx * 2);
            }
#pragma unroll
            for (int r = 0; r < 8; r++) {
                float2 sf = upk(sp[r]);
                unsigned long long s0 = dupf(sf.x), s1 = dupf(sf.y);
#pragma unroll
                for (int g = 0; g < 4; g++) {
                    fma2(oacc[r][g], s0, v0[g]);
                    fma2(oacc[r][g], s1, v1[g]);
                }
            }
        }
    }

    // ---- RMSNorm over D2=128 and store ----
    float* obase = out + (bh * S_LEN + i0) * DHEAD;
#pragma unroll
    for (int r = 0; r < 8; r++) {
        float2 a0 = upk(oacc[r][0]), a1 = upk(oacc[r][1]);
        float2 a2 = upk(oacc[r][2]), a3 = upk(oacc[r][3]);
        float ss = a0.x * a0.x + a0.y * a0.y + a1.x * a1.x + a1.y * a1.y +
                   a2.x * a2.x + a2.y * a2.y + a3.x * a3.x + a3.y * a3.y;
#pragma unroll
        for (int off = 1; off < 16; off <<= 1) ss += __shfl_xor_sync(0xffffffffu, ss, off);
        float sc = rsqrtf(ss * (1.f / 128.f) + 1e-6f);
        float* op = obase + (size_t)(ty * 8 + r) * DHEAD + tx * 2;
        *(float2*)(op) = make_float2(a0.x * sc, a0.y * sc);
        *(float2*)(op + 32) = make_float2(a1.x * sc, a1.y * sc);
        *(float2*)(op + 64) = make_float2(a2.x * sc, a2.y * sc);
        *(float2*)(op + 96) = make_float2(a3.x * sc, a3.y * sc);
    }
}

extern "C" void kernel_launch(void* const* d_in, const int* in_sizes, int n_in,
                              void* d_out, int out_size) {
    const float* q = (const float*)d_in[0];
    const float* k = (const float*)d_in[1];
    const float* v = (const float*)d_in[2];
    const float* omask = (const float*)d_in[3];
    float* out = (float*)d_out;

    cudaFuncSetAttribute(retention_kernel, cudaFuncAttributeMaxDynamicSharedMemorySize,
                         SMEM_BYTES);

    rnorm_kernel<<<HEADS * S_LEN, 256>>>(omask);
    retention_kernel<<<dim3(S_LEN / BM, HEADS, BATCH), THREADS, SMEM_BYTES>>>(q, k, v,
                                                                              omask, out);
}

// round 4
// speedup vs baseline: 2.5211x; 2.2958x over previous
#include <cuda_runtime.h>
#include <cuda_bf16.h>
#include <cstdint>

#define S_LEN 2048
#define HEADS 8
#define BATCH 2
#define DHEAD 128
#define BM 128
#define BN 64
#define NJT (S_LEN / BN)
#define THREADS 256

// smem byte regions
#define SM_QHI 0
#define SM_QLO 32768
#define SM_K 65536    // buf b: +b*32768, hi +0, lo +16384
#define SM_V 131072   // buf b: +b*32768, hi +0, lo +16384
#define SM_S 196608   // hi +0, lo +16384
#define SM_SLO (SM_S + 16384)
#define SMEM_TOTAL 229376

__device__ float g_rnorm[HEADS * S_LEN];

__device__ __forceinline__ uint32_t smem_u32(const void* p) {
    uint32_t a;
    asm("{ .reg .u64 t; cvta.to.shared.u64 t, %1; cvt.u32.u64 %0, t; }" : "=r"(a) : "l"(p));
    return a;
}

// pack (e0,e1) -> bf16x2 hi, residual bf16x2 lo  (reg.lo = elem0, reg.hi = elem1)
__device__ __forceinline__ void split2(float e0, float e1, uint32_t& hi, uint32_t& lo) {
    asm("cvt.rn.bf16x2.f32 %0, %1, %2;" : "=r"(hi) : "f"(e1), "f"(e0));
    float f0 = __uint_as_float(hi << 16);
    float f1 = __uint_as_float(hi & 0xffff0000u);
    asm("cvt.rn.bf16x2.f32 %0, %1, %2;" : "=r"(lo) : "f"(e1 - f1), "f"(e0 - f0));
}

__device__ __forceinline__ void ldmx4(uint32_t& r0, uint32_t& r1, uint32_t& r2, uint32_t& r3,
                                      uint32_t a) {
    asm volatile("ldmatrix.sync.aligned.m8n8.x4.shared.b16 {%0,%1,%2,%3}, [%4];"
                 : "=r"(r0), "=r"(r1), "=r"(r2), "=r"(r3) : "r"(a));
}

__device__ __forceinline__ void mmab(float* c, const uint32_t* a, uint32_t b0, uint32_t b1) {
    asm volatile(
        "mma.sync.aligned.m16n8k16.row.col.f32.bf16.bf16.f32 "
        "{%0,%1,%2,%3},{%4,%5,%6,%7},{%8,%9},{%0,%1,%2,%3};"
        : "+f"(c[0]), "+f"(c[1]), "+f"(c[2]), "+f"(c[3])
        : "r"(a[0]), "r"(a[1]), "r"(a[2]), "r"(a[3]), "r"(b0), "r"(b1));
}

// ---------------- rnorm: rsqrt(sum_j omask[h,i,j]) ----------------
__global__ void rnorm_kernel(const float* __restrict__ omask) {
    int row = blockIdx.x;
    const float* p = omask + (size_t)row * S_LEN;
    float s = 0.f;
    for (int j = threadIdx.x * 4; j < S_LEN; j += 256 * 4) {
        float4 f = *(const float4*)(p + j);
        s += f.x + f.y + f.z + f.w;
    }
#pragma unroll
    for (int off = 16; off > 0; off >>= 1) s += __shfl_xor_sync(0xffffffffu, s, off);
    __shared__ float red[8];
    if ((threadIdx.x & 31) == 0) red[threadIdx.x >> 5] = s;
    __syncthreads();
    if (threadIdx.x == 0) {
        float t = 0.f;
#pragma unroll
        for (int i = 0; i < 8; i++) t += red[i];
        g_rnorm[row] = (t > 0.f) ? rsqrtf(t) : 0.f;
    }
}

// load K (64x128) and V^T (128x64) tiles, bf16-split, into buf
__device__ __forceinline__ void load_kv(char* smc, const float* kb, const float* vb, int buf,
                                        int tid, int wid, int lane) {
    char* kh = smc + SM_K + buf * 32768;
    char* kl = kh + 16384;
#pragma unroll
    for (int x = tid; x < 64 * 32; x += THREADS) {
        int r = x >> 5, c4 = (x & 31) << 2;
        float4 f = *(const float4*)(kb + r * DHEAD + c4);
        uint32_t h0, l0, h1, l1;
        split2(f.x, f.y, h0, l0);
        split2(f.z, f.w, h1, l1);
        int off = r * 256 + ((((c4 >> 3)) ^ (r & 7)) << 4) + (c4 & 7) * 2;
        *(uint2*)(kh + off) = make_uint2(h0, h1);
        *(uint2*)(kl + off) = make_uint2(l0, l1);
    }
    char* vh = smc + SM_V + buf * 32768;
    char* vl = vh + 16384;
    int d = ((wid & 3) << 5) + lane;
#pragma unroll
    for (int jp = (wid >> 2); jp < 32; jp += 2) {
        float a = vb[(size_t)(2 * jp) * DHEAD + d];
        float b2 = vb[(size_t)(2 * jp + 1) * DHEAD + d];
        uint32_t hh, ll;
        split2(a, b2, hh, ll);
        int off = d * 128 + (((jp >> 2) ^ (d & 7)) << 4) + ((2 * jp) & 7) * 2;
        *(uint32_t*)(vh + off) = hh;
        *(uint32_t*)(vl + off) = ll;
    }
}

__global__ __launch_bounds__(THREADS, 1)
void retention_mma_kernel(const float* __restrict__ q, const float* __restrict__ k,
                          const float* __restrict__ v, const float* __restrict__ omask,
                          float* __restrict__ out) {
    extern __shared__ char smc[];
    const uint32_t su = smem_u32(smc);
    const int tid = threadIdx.x;
    const int wid = tid >> 5, lane = tid & 31;
    const int mw = wid & 3, nw = wid >> 2;

    const int it = blockIdx.x, h = blockIdx.y, b = blockIdx.z;
    const int i0 = it * BM;
    const size_t bh = (size_t)(b * HEADS + h);
    const float* qbase = q + (bh * S_LEN + i0) * DHEAD;
    const float* kbase = k + bh * S_LEN * DHEAD;
    const float* vbase = v + bh * S_LEN * DHEAD;
    const float* mbase = omask + ((size_t)h * S_LEN + i0) * S_LEN;

    // ---- Q tile [128x128] -> bf16 hi/lo, swizzled K-major ----
#pragma unroll
    for (int x = tid; x < 128 * 32; x += THREADS) {
        int r = x >> 5, c4 = (x & 31) << 2;
        float4 f = *(const float4*)(qbase + r * DHEAD + c4);
        uint32_t h0, l0, h1, l1;
        split2(f.x, f.y, h0, l0);
        split2(f.z, f.w, h1, l1);
        int off = r * 256 + ((((c4 >> 3)) ^ (r & 7)) << 4) + (c4 & 7) * 2;
        *(uint2*)(smc + SM_QHI + off) = make_uint2(h0, h1);
        *(uint2*)(smc + SM_QLO + off) = make_uint2(l0, l1);
    }

    // rn for this thread's 4 output rows
    float rnv[2][2];
#pragma unroll
    for (int mt = 0; mt < 2; mt++) {
        int r0 = mw * 32 + mt * 16 + (lane >> 2);
        rnv[mt][0] = g_rnorm[h * S_LEN + i0 + r0];
        rnv[mt][1] = g_rnorm[h * S_LEN + i0 + r0 + 8];
    }

    load_kv(smc, kbase, vbase, 0, tid, wid, lane);
    __syncthreads();

    float oacc[2][8][4];
#pragma unroll
    for (int mt = 0; mt < 2; mt++)
#pragma unroll
        for (int nt = 0; nt < 8; nt++)
#pragma unroll
            for (int e = 0; e < 4; e++) oacc[mt][nt][e] = 0.f;

    for (int jt = 0; jt < NJT; jt++) {
        const int buf = jt & 1;
        if (jt + 1 < NJT)
            load_kv(smc, kbase + (size_t)(jt + 1) * BN * DHEAD,
                    vbase + (size_t)(jt + 1) * BN * DHEAD, buf ^ 1, tid, wid, lane);

        // ---- GEMM1: S = Q @ K^T (bf16x3) ----
        float sacc[2][4][4];
#pragma unroll
        for (int mt = 0; mt < 2; mt++)
#pragma unroll
            for (int nt = 0; nt < 4; nt++)
#pragma unroll
                for (int e = 0; e < 4; e++) sacc[mt][nt][e] = 0.f;

        const uint32_t khb = su + SM_K + buf * 32768, klb = khb + 16384;
#pragma unroll
        for (int ks = 0; ks < 8; ks++) {
            const int c0 = 2 * ks;
            uint32_t qh[2][4], ql[2][4];
#pragma unroll
            for (int mt = 0; mt < 2; mt++) {
                int row = mw * 32 + mt * 16 + (lane & 15);
                int ch = (c0 + (lane >> 4)) ^ (row & 7);
                uint32_t off = row * 256 + (ch << 4);
                ldmx4(qh[mt][0], qh[mt][1], qh[mt][2], qh[mt][3], su + SM_QHI + off);
                ldmx4(ql[mt][0], ql[mt][1], ql[mt][2], ql[mt][3], su + SM_QLO + off);
            }
#pragma unroll
            for (int np = 0; np < 2; np++) {
                int row = nw * 32 + np * 16 + (lane & 7) + ((lane >> 4) << 3);
                int ch = (c0 + ((lane >> 3) & 1)) ^ (row & 7);
                uint32_t off = row * 256 + (ch << 4);
                uint32_t h0, h1, h2, h3, l0, l1, l2, l3;
                ldmx4(h0, h1, h2, h3, khb + off);
                ldmx4(l0, l1, l2, l3, klb + off);
#pragma unroll
                for (int mt = 0; mt < 2; mt++) {
                    mmab(sacc[mt][2 * np], qh[mt], h0, h1);
                    mmab(sacc[mt][2 * np + 1], qh[mt], h2, h3);
                    mmab(sacc[mt][2 * np], qh[mt], l0, l1);
                    mmab(sacc[mt][2 * np + 1], qh[mt], l2, l3);
                    mmab(sacc[mt][2 * np], ql[mt], h0, h1);
                    mmab(sacc[mt][2 * np + 1], ql[mt], h2, h3);
                }
            }
        }

        // ---- epilogue: *mask*rn, split -> S smem ----
#pragma unroll
        for (int mt = 0; mt < 2; mt++) {
            int m0 = mw * 32 + mt * 16 + (lane >> 2);
            int m1 = m0 + 8;
#pragma unroll
            for (int nt = 0; nt < 4; nt++) {
                int jl = nw * 32 + nt * 8 + (lane & 3) * 2;
                const float* mp = mbase + (size_t)m0 * S_LEN + jt * BN + jl;
                float2 mk0 = *(const float2*)mp;
                float2 mk1 = *(const float2*)(mp + 8 * S_LEN);
                float s0 = sacc[mt][nt][0] * mk0.x * rnv[mt][0];
                float s1 = sacc[mt][nt][1] * mk0.y * rnv[mt][0];
                float s2 = sacc[mt][nt][2] * mk1.x * rnv[mt][1];
                float s3 = sacc[mt][nt][3] * mk1.y * rnv[mt][1];
                uint32_t hh, ll;
                split2(s0, s1, hh, ll);
                int off = m0 * 128 + (((jl >> 3) ^ (m0 & 7)) << 4) + (jl & 7) * 2;
                *(uint32_t*)(smc + SM_S + off) = hh;
                *(uint32_t*)(smc + SM_SLO + off) = ll;
                split2(s2, s3, hh, ll);
                off = m1 * 128 + (((jl >> 3) ^ (m1 & 7)) << 4) + (jl & 7) * 2;
                *(uint32_t*)(smc + SM_S + off) = hh;
                *(uint32_t*)(smc + SM_SLO + off) = ll;
            }
        }
        __syncthreads();

        // ---- GEMM2: O += S @ V (bf16x3) ----
        const uint32_t vhb = su + SM_V + buf * 32768, vlb = vhb + 16384;
#pragma unroll
        for (int ks = 0; ks < 4; ks++) {
            const int c0 = 2 * ks;
            uint32_t sh[2][4], sl[2][4];
#pragma unroll
            for (int mt = 0; mt < 2; mt++) {
                int row = mw * 32 + mt * 16 + (lane & 15);
                int ch = (c0 + (lane >> 4)) ^ (row & 7);
                uint32_t off = row * 128 + (ch << 4);
                ldmx4(sh[mt][0], sh[mt][1], sh[mt][2], sh[mt][3], su + SM_S + off);
                ldmx4(sl[mt][0], sl[mt][1], sl[mt][2], sl[mt][3], su + SM_SLO + off);
            }
#pragma unroll
            for (int np = 0; np < 4; np++) {
                int row = nw * 64 + np * 16 + (lane & 7) + ((lane >> 4) << 3);
                int ch = (c0 + ((lane >> 3) & 1)) ^ (row & 7);
                uint32_t off = row * 128 + (ch << 4);
                uint32_t h0, h1, h2, h3, l0, l1, l2, l3;
                ldmx4(h0, h1, h2, h3, vhb + off);
                ldmx4(l0, l1, l2, l3, vlb + off);
#pragma unroll
                for (int mt = 0; mt < 2; mt++) {
                    mmab(oacc[mt][2 * np], sh[mt], h0, h1);
                    mmab(oacc[mt][2 * np + 1], sh[mt], h2, h3);
                    mmab(oacc[mt][2 * np], sh[mt], l0, l1);
                    mmab(oacc[mt][2 * np + 1], sh[mt], l2, l3);
                    mmab(oacc[mt][2 * np], sl[mt], h0, h1);
                    mmab(oacc[mt][2 * np + 1], sl[mt], h2, h3);
                }
            }
        }
        __syncthreads();
    }

    // ---- RMSNorm + store ----
    float* rows2 = (float*)(smc + SM_S);
#pragma unroll
    for (int mt = 0; mt < 2; mt++) {
        float p0 = 0.f, p1 = 0.f;
#pragma unroll
        for (int nt = 0; nt < 8; nt++) {
            p0 += oacc[mt][nt][0] * oacc[mt][nt][0] + oacc[mt][nt][1] * oacc[mt][nt][1];
            p1 += oacc[mt][nt][2] * oacc[mt][nt][2] + oacc[mt][nt][3] * oacc[mt][nt][3];
        }
        p0 += __shfl_xor_sync(0xffffffffu, p0, 1);
        p0 += __shfl_xor_sync(0xffffffffu, p0, 2);
        p1 += __shfl_xor_sync(0xffffffffu, p1, 1);
        p1 += __shfl_xor_sync(0xffffffffu, p1, 2);
        if ((lane & 3) == 0) {
            int m0 = mw * 32 + mt * 16 + (lane >> 2);
            rows2[m0 * 2 + nw] = p0;
            rows2[(m0 + 8) * 2 + nw] = p1;
        }
    }
    __syncthreads();
#pragma unroll
    for (int mt = 0; mt < 2; mt++) {
        int m0 = mw * 32 + mt * 16 + (lane >> 2);
        float sc0 = rsqrtf((rows2[m0 * 2] + rows2[m0 * 2 + 1]) * (1.f / 128.f) + 1e-6f);
        float sc1 =
            rsqrtf((rows2[(m0 + 8) * 2] + rows2[(m0 + 8) * 2 + 1]) * (1.f / 128.f) + 1e-6f);
        float* o0 = out + (bh * S_LEN + i0 + m0) * DHEAD + nw * 64 + (lane & 3) * 2;
        float* o1 = o0 + 8 * DHEAD;
#pragma unroll
        for (int nt = 0; nt < 8; nt++) {
            *(float2*)(o0 + nt * 8) =
                make_float2(oacc[mt][nt][0] * sc0, oacc[mt][nt][1] * sc0);
            *(float2*)(o1 + nt * 8) =
                make_float2(oacc[mt][nt][2] * sc1, oacc[mt][nt][3] * sc1);
        }
    }
}

extern "C" void kernel_launch(void* const* d_in, const int* in_sizes, int n_in,
                              void* d_out, int out_size) {
    const float* q = (const float*)d_in[0];
    const float* k = (const float*)d_in[1];
    const float* v = (const float*)d_in[2];
    const float* omask = (const float*)d_in[3];
    float* out = (float*)d_out;

    cudaFuncSetAttribute(retention_mma_kernel, cudaFuncAttributeMaxDynamicSharedMemorySize,
                         SMEM_TOTAL);

    rnorm_kernel<<<HEADS * S_LEN, 256>>>(omask);
    retention_mma_kernel<<<dim3(S_LEN / BM, HEADS, BATCH), THREADS, SMEM_TOTAL>>>(
        q, k, v, omask, out);
}

// round 5
// speedup vs baseline: 2.9866x; 1.1846x over previous
#include <cuda_runtime.h>
#include <cuda_bf16.h>
#include <cstdint>

#define S_LEN 2048
#define HEADS 8
#define BATCH 2
#define DHEAD 128
#define BM 128
#define BN 64
#define NJT (S_LEN / BN)
#define THREADS 256

// smem byte regions (tiles: row stride 256B = 128 bf16 cols)
#define SM_QHI 0
#define SM_QLO 32768
#define SM_K 65536   // + buf*32768 : hi, +16384 : lo
#define SM_V 131072  // + buf*32768 : hi, +16384 : lo
#define SMEM_TOTAL 196608

__device__ float g_rnorm[HEADS * S_LEN];

__device__ __forceinline__ uint32_t smem_u32(const void* p) {
    uint32_t a;
    asm("{ .reg .u64 t; cvta.to.shared.u64 t, %1; cvt.u32.u64 %0, t; }" : "=r"(a) : "l"(p));
    return a;
}

// pack (e0,e1) -> bf16x2 hi (lo-half=e0), residual bf16x2 lo
__device__ __forceinline__ void split2(float e0, float e1, uint32_t& hi, uint32_t& lo) {
    asm("cvt.rn.bf16x2.f32 %0, %1, %2;" : "=r"(hi) : "f"(e1), "f"(e0));
    float f0 = __uint_as_float(hi << 16);
    float f1 = __uint_as_float(hi & 0xffff0000u);
    asm("cvt.rn.bf16x2.f32 %0, %1, %2;" : "=r"(lo) : "f"(e1 - f1), "f"(e0 - f0));
}

__device__ __forceinline__ void ldmx4(uint32_t& r0, uint32_t& r1, uint32_t& r2, uint32_t& r3,
                                      uint32_t a) {
    asm volatile("ldmatrix.sync.aligned.m8n8.x4.shared.b16 {%0,%1,%2,%3}, [%4];"
                 : "=r"(r0), "=r"(r1), "=r"(r2), "=r"(r3) : "r"(a));
}
__device__ __forceinline__ void ldmx4t(uint32_t& r0, uint32_t& r1, uint32_t& r2, uint32_t& r3,
                                       uint32_t a) {
    asm volatile("ldmatrix.sync.aligned.m8n8.x4.trans.shared.b16 {%0,%1,%2,%3}, [%4];"
                 : "=r"(r0), "=r"(r1), "=r"(r2), "=r"(r3) : "r"(a));
}

__device__ __forceinline__ void mmab(float* c, const uint32_t* a, uint32_t b0, uint32_t b1) {
    asm volatile(
        "mma.sync.aligned.m16n8k16.row.col.f32.bf16.bf16.f32 "
        "{%0,%1,%2,%3},{%4,%5,%6,%7},{%8,%9},{%0,%1,%2,%3};"
        : "+f"(c[0]), "+f"(c[1]), "+f"(c[2]), "+f"(c[3])
        : "r"(a[0]), "r"(a[1]), "r"(a[2]), "r"(a[3]), "r"(b0), "r"(b1));
}

// ---------------- rnorm: rsqrt(sum_j omask[h,i,j]) ----------------
__global__ void rnorm_kernel(const float* __restrict__ omask) {
    int row = blockIdx.x;
    const float* p = omask + (size_t)row * S_LEN;
    float s = 0.f;
    for (int j = threadIdx.x * 4; j < S_LEN; j += 256 * 4) {
        float4 f = *(const float4*)(p + j);
        s += f.x + f.y + f.z + f.w;
    }
#pragma unroll
    for (int off = 16; off > 0; off >>= 1) s += __shfl_xor_sync(0xffffffffu, s, off);
    __shared__ float red[8];
    if ((threadIdx.x & 31) == 0) red[threadIdx.x >> 5] = s;
    __syncthreads();
    if (threadIdx.x == 0) {
        float t = 0.f;
#pragma unroll
        for (int i = 0; i < 8; i++) t += red[i];
        g_rnorm[row] = (t > 0.f) ? rsqrtf(t) : 0.f;
    }
}

// direct LDG->split->STS of a 64x128 fp32 tile into hi/lo bf16 smem (swizzled)
__device__ __forceinline__ void load_tile(const float* __restrict__ src, char* hi, char* lo,
                                          int tid) {
#pragma unroll
    for (int i = 0; i < 8; i++) {
        int x = tid + i * THREADS;
        int r = x >> 5, c4 = (x & 31) << 2;
        float4 f = *(const float4*)(src + r * DHEAD + c4);
        uint32_t h0, l0, h1, l1;
        split2(f.x, f.y, h0, l0);
        split2(f.z, f.w, h1, l1);
        int off = r * 256 + ((((c4 >> 3)) ^ (r & 7)) << 4) + (c4 & 7) * 2;
        *(uint2*)(hi + off) = make_uint2(h0, h1);
        *(uint2*)(lo + off) = make_uint2(l0, l1);
    }
}

__global__ __launch_bounds__(THREADS, 1)
void retention_mma_kernel(const float* __restrict__ q, const float* __restrict__ k,
                          const float* __restrict__ v, const float* __restrict__ omask,
                          float* __restrict__ out) {
    extern __shared__ char smc[];
    const uint32_t su = smem_u32(smc);
    const int tid = threadIdx.x;
    const int wid = tid >> 5, lane = tid & 31;
    const int m0 = wid * 16;  // each warp owns rows m0..m0+15, full width
    const int g = lane >> 2;

    const int it = blockIdx.x, h = blockIdx.y, b = blockIdx.z;
    const int i0 = it * BM;
    const size_t bh = (size_t)(b * HEADS + h);
    const float* qbase = q + (bh * S_LEN + i0) * DHEAD;
    const float* kbase = k + bh * S_LEN * DHEAD;
    const float* vbase = v + bh * S_LEN * DHEAD;
    const float* mbase = omask + ((size_t)h * S_LEN + i0) * S_LEN;

    // ---- Q tile [128x128] -> bf16 hi/lo ----
#pragma unroll
    for (int x = tid; x < 128 * 32; x += THREADS) {
        int r = x >> 5, c4 = (x & 31) << 2;
        float4 f = *(const float4*)(qbase + r * DHEAD + c4);
        uint32_t h0, l0, h1, l1;
        split2(f.x, f.y, h0, l0);
        split2(f.z, f.w, h1, l1);
        int off = r * 256 + ((((c4 >> 3)) ^ (r & 7)) << 4) + (c4 & 7) * 2;
        *(uint2*)(smc + SM_QHI + off) = make_uint2(h0, h1);
        *(uint2*)(smc + SM_QLO + off) = make_uint2(l0, l1);
    }
    // ---- K/V tile 0 ----
    load_tile(kbase, smc + SM_K, smc + SM_K + 16384, tid);
    load_tile(vbase, smc + SM_V, smc + SM_V + 16384, tid);

    const float rn0 = g_rnorm[h * S_LEN + i0 + m0 + g];
    const float rn1 = g_rnorm[h * S_LEN + i0 + m0 + g + 8];

    float oacc[16][4];
#pragma unroll
    for (int nt = 0; nt < 16; nt++)
#pragma unroll
        for (int e = 0; e < 4; e++) oacc[nt][e] = 0.f;

    __syncthreads();

    for (int jt = 0; jt < NJT; jt++) {
        const int buf = jt & 1;
        const bool pf = (jt + 1 < NJT);
        char* khn = smc + SM_K + (buf ^ 1) * 32768;
        char* vhn = smc + SM_V + (buf ^ 1) * 32768;
        const float* kbn = kbase + (size_t)(jt + 1) * BN * DHEAD;
        const float* vbn = vbase + (size_t)(jt + 1) * BN * DHEAD;

        // ---- prefetch next K tile into regs ----
        float4 kreg[8];
        if (pf) {
#pragma unroll
            for (int i = 0; i < 8; i++) {
                int x = tid + i * THREADS;
                kreg[i] = *(const float4*)(kbn + (x >> 5) * DHEAD + ((x & 31) << 2));
            }
        }
        // ---- prefetch mask into regs ----
        const float* mp = mbase + (size_t)(m0 + g) * S_LEN + jt * BN + (lane & 3) * 2;
        float2 mk0[8], mk1[8];
#pragma unroll
        for (int nt = 0; nt < 8; nt++) {
            mk0[nt] = *(const float2*)(mp + nt * 8);
            mk1[nt] = *(const float2*)(mp + 8 * S_LEN + nt * 8);
        }

        // ---- GEMM1: S[m16][j64] = Q @ K^T (bf16x3) ----
        float sacc[8][4];
#pragma unroll
        for (int nt = 0; nt < 8; nt++)
#pragma unroll
            for (int e = 0; e < 4; e++) sacc[nt][e] = 0.f;

        const uint32_t khb = su + SM_K + buf * 32768, klb = khb + 16384;
        const int qrow = m0 + (lane & 15);
        const int krow_b = (lane & 7) + ((lane >> 4) << 3);
#pragma unroll
        for (int ks = 0; ks < 8; ks++) {
            uint32_t qoff = qrow * 256 + (((2 * ks + (lane >> 4)) ^ (qrow & 7)) << 4);
            uint32_t qh[4], ql[4];
            ldmx4(qh[0], qh[1], qh[2], qh[3], su + SM_QHI + qoff);
            ldmx4(ql[0], ql[1], ql[2], ql[3], su + SM_QLO + qoff);
#pragma unroll
            for (int np = 0; np < 4; np++) {
                int krow = np * 16 + krow_b;
                uint32_t koff =
                    krow * 256 + (((2 * ks + ((lane >> 3) & 1)) ^ (krow & 7)) << 4);
                uint32_t h0, h1, h2, h3, l0, l1, l2, l3;
                ldmx4(h0, h1, h2, h3, khb + koff);
                ldmx4(l0, l1, l2, l3, klb + koff);
                mmab(sacc[2 * np], qh, h0, h1);
                mmab(sacc[2 * np + 1], qh, h2, h3);
                mmab(sacc[2 * np], qh, l0, l1);
                mmab(sacc[2 * np + 1], qh, l2, l3);
                mmab(sacc[2 * np], ql, h0, h1);
                mmab(sacc[2 * np + 1], ql, h2, h3);
            }
        }

        // ---- store prefetched K (regs -> smem) ----
        if (pf) {
#pragma unroll
            for (int i = 0; i < 8; i++) {
                int x = tid + i * THREADS;
                int r = x >> 5, c4 = (x & 31) << 2;
                uint32_t h0, l0, h1, l1;
                split2(kreg[i].x, kreg[i].y, h0, l0);
                split2(kreg[i].z, kreg[i].w, h1, l1);
                int off = r * 256 + ((((c4 >> 3)) ^ (r & 7)) << 4) + (c4 & 7) * 2;
                *(uint2*)(khn + off) = make_uint2(h0, h1);
                *(uint2*)(khn + 16384 + off) = make_uint2(l0, l1);
            }
        }
        // ---- prefetch next V tile into regs ----
        float4 vreg[8];
        if (pf) {
#pragma unroll
            for (int i = 0; i < 8; i++) {
                int x = tid + i * THREADS;
                vreg[i] = *(const float4*)(vbn + (x >> 5) * DHEAD + ((x & 31) << 2));
            }
        }

        // ---- epilogue in registers: S * mask * rn -> bf16 A-fragments ----
        uint32_t ah[4][4], al[4][4];
#pragma unroll
        for (int kt = 0; kt < 4; kt++) {
            split2(sacc[2 * kt][0] * mk0[2 * kt].x * rn0,
                   sacc[2 * kt][1] * mk0[2 * kt].y * rn0, ah[kt][0], al[kt][0]);
            split2(sacc[2 * kt][2] * mk1[2 * kt].x * rn1,
                   sacc[2 * kt][3] * mk1[2 * kt].y * rn1, ah[kt][1], al[kt][1]);
            split2(sacc[2 * kt + 1][0] * mk0[2 * kt + 1].x * rn0,
                   sacc[2 * kt + 1][1] * mk0[2 * kt + 1].y * rn0, ah[kt][2], al[kt][2]);
            split2(sacc[2 * kt + 1][2] * mk1[2 * kt + 1].x * rn1,
                   sacc[2 * kt + 1][3] * mk1[2 * kt + 1].y * rn1, ah[kt][3], al[kt][3]);
        }

        // ---- GEMM2: O[m16][d128] += S @ V (bf16x3, B via ldmatrix.trans) ----
        const uint32_t vhb = su + SM_V + buf * 32768, vlb = vhb + 16384;
#pragma unroll
        for (int kt = 0; kt < 4; kt++) {
            const int vrow = kt * 16 + (lane & 15);
#pragma unroll
            for (int np = 0; np < 8; np++) {
                uint32_t voff = vrow * 256 + (((2 * np + (lane >> 4)) ^ (vrow & 7)) << 4);
                uint32_t h0, h1, h2, h3, l0, l1, l2, l3;
                ldmx4t(h0, h1, h2, h3, vhb + voff);
                ldmx4t(l0, l1, l2, l3, vlb + voff);
                mmab(oacc[2 * np], ah[kt], h0, h1);
                mmab(oacc[2 * np + 1], ah[kt], h2, h3);
                mmab(oacc[2 * np], ah[kt], l0, l1);
                mmab(oacc[2 * np + 1], ah[kt], l2, l3);
                mmab(oacc[2 * np], al[kt], h0, h1);
                mmab(oacc[2 * np + 1], al[kt], h2, h3);
            }
        }

        // ---- store prefetched V ----
        if (pf) {
#pragma unroll
            for (int i = 0; i < 8; i++) {
                int x = tid + i * THREADS;
                int r = x >> 5, c4 = (x & 31) << 2;
                uint32_t h0, l0, h1, l1;
                split2(vreg[i].x, vreg[i].y, h0, l0);
                split2(vreg[i].z, vreg[i].w, h1, l1);
                int off = r * 256 + ((((c4 >> 3)) ^ (r & 7)) << 4) + (c4 & 7) * 2;
                *(uint2*)(vhn + off) = make_uint2(h0, h1);
                *(uint2*)(vhn + 16384 + off) = make_uint2(l0, l1);
            }
        }
        __syncthreads();
    }

    // ---- RMSNorm (warp-local, full row in one warp) + store ----
    float p0 = 0.f, p1 = 0.f;
#pragma unroll
    for (int nt = 0; nt < 16; nt++) {
        p0 += oacc[nt][0] * oacc[nt][0] + oacc[nt][1] * oacc[nt][1];
        p1 += oacc[nt][2] * oacc[nt][2] + oacc[nt][3] * oacc[nt][3];
    }
    p0 += __shfl_xor_sync(0xffffffffu, p0, 1);
    p0 += __shfl_xor_sync(0xffffffffu, p0, 2);
    p1 += __shfl_xor_sync(0xffffffffu, p1, 1);
    p1 += __shfl_xor_sync(0xffffffffu, p1, 2);
    float sc0 = rsqrtf(p0 * (1.f / 128.f) + 1e-6f);
    float sc1 = rsqrtf(p1 * (1.f / 128.f) + 1e-6f);
    float* o0 = out + (bh * S_LEN + i0 + m0 + g) * DHEAD + (lane & 3) * 2;
    float* o1 = o0 + 8 * DHEAD;
#pragma unroll
    for (int nt = 0; nt < 16; nt++) {
        *(float2*)(o0 + nt * 8) = make_float2(oacc[nt][0] * sc0, oacc[nt][1] * sc0);
        *(float2*)(o1 + nt * 8) = make_float2(oacc[nt][2] * sc1, oacc[nt][3] * sc1);
    }
}

extern "C" void kernel_launch(void* const* d_in, const int* in_sizes, int n_in,
                              void* d_out, int out_size) {
    const float* q = (const float*)d_in[0];
    const float* k = (const float*)d_in[1];
    const float* v = (const float*)d_in[2];
    const float* omask = (const float*)d_in[3];
    float* out = (float*)d_out;

    cudaFuncSetAttribute(retention_mma_kernel, cudaFuncAttributeMaxDynamicSharedMemorySize,
                         SMEM_TOTAL);

    rnorm_kernel<<<HEADS * S_LEN, 256>>>(omask);
    retention_mma_kernel<<<dim3(S_LEN / BM, HEADS, BATCH), THREADS, SMEM_TOTAL>>>(
        q, k, v, omask, out);
}

// round 6
// speedup vs baseline: 3.0995x; 1.0378x over previous
#include <cuda_runtime.h>
#include <cuda_bf16.h>
#include <cstdint>

#define S_LEN 2048
#define HEADS 8
#define BATCH 2
#define DHEAD 128
#define BM 256
#define BN 64
#define NJT (S_LEN / BN)
#define THREADS 256

// smem byte regions (tiles: row stride 256B = 128 bf16 cols)
#define SM_QHI 0
#define SM_QLO 65536
#define SM_K 131072  // + buf*32768 : hi, +16384 : lo
#define SM_V 196608  // hi, +16384 : lo
#define SMEM_TOTAL 229376

__device__ float g_rnorm[HEADS * S_LEN];

__device__ __forceinline__ uint32_t smem_u32(const void* p) {
    uint32_t a;
    asm("{ .reg .u64 t; cvta.to.shared.u64 t, %1; cvt.u32.u64 %0, t; }" : "=r"(a) : "l"(p));
    return a;
}

// pack (e0,e1) -> bf16x2 hi (lo-half=e0), residual bf16x2 lo
__device__ __forceinline__ void split2(float e0, float e1, uint32_t& hi, uint32_t& lo) {
    asm("cvt.rn.bf16x2.f32 %0, %1, %2;" : "=r"(hi) : "f"(e1), "f"(e0));
    float f0 = __uint_as_float(hi << 16);
    float f1 = __uint_as_float(hi & 0xffff0000u);
    asm("cvt.rn.bf16x2.f32 %0, %1, %2;" : "=r"(lo) : "f"(e1 - f1), "f"(e0 - f0));
}

__device__ __forceinline__ void ldmx4(uint32_t& r0, uint32_t& r1, uint32_t& r2, uint32_t& r3,
                                      uint32_t a) {
    asm volatile("ldmatrix.sync.aligned.m8n8.x4.shared.b16 {%0,%1,%2,%3}, [%4];"
                 : "=r"(r0), "=r"(r1), "=r"(r2), "=r"(r3) : "r"(a));
}
__device__ __forceinline__ void ldmx4t(uint32_t& r0, uint32_t& r1, uint32_t& r2, uint32_t& r3,
                                       uint32_t a) {
    asm volatile("ldmatrix.sync.aligned.m8n8.x4.trans.shared.b16 {%0,%1,%2,%3}, [%4];"
                 : "=r"(r0), "=r"(r1), "=r"(r2), "=r"(r3) : "r"(a));
}

__device__ __forceinline__ void mmab(float* c, const uint32_t* a, uint32_t b0, uint32_t b1) {
    asm volatile(
        "mma.sync.aligned.m16n8k16.row.col.f32.bf16.bf16.f32 "
        "{%0,%1,%2,%3},{%4,%5,%6,%7},{%8,%9},{%0,%1,%2,%3};"
        : "+f"(c[0]), "+f"(c[1]), "+f"(c[2]), "+f"(c[3])
        : "r"(a[0]), "r"(a[1]), "r"(a[2]), "r"(a[3]), "r"(b0), "r"(b1));
}

// ---------------- rnorm: rsqrt(sum_j omask[h,i,j]) ----------------
__global__ void rnorm_kernel(const float* __restrict__ omask) {
    int row = blockIdx.x;
    const float* p = omask + (size_t)row * S_LEN;
    float s = 0.f;
    for (int j = threadIdx.x * 4; j < S_LEN; j += 256 * 4) {
        float4 f = *(const float4*)(p + j);
        s += f.x + f.y + f.z + f.w;
    }
#pragma unroll
    for (int off = 16; off > 0; off >>= 1) s += __shfl_xor_sync(0xffffffffu, s, off);
    __shared__ float red[8];
    if ((threadIdx.x & 31) == 0) red[threadIdx.x >> 5] = s;
    __syncthreads();
    if (threadIdx.x == 0) {
        float t = 0.f;
#pragma unroll
        for (int i = 0; i < 8; i++) t += red[i];
        g_rnorm[row] = (t > 0.f) ? rsqrtf(t) : 0.f;
    }
}

// direct LDG->split->STS of a 64x128 fp32 tile into hi/lo bf16 smem (swizzled)
__device__ __forceinline__ void load_tile(const float* __restrict__ src, char* hi, char* lo,
                                          int tid) {
#pragma unroll
    for (int i = 0; i < 8; i++) {
        int x = tid + i * THREADS;
        int r = x >> 5, c4 = (x & 31) << 2;
        float4 f = *(const float4*)(src + r * DHEAD + c4);
        uint32_t h0, l0, h1, l1;
        split2(f.x, f.y, h0, l0);
        split2(f.z, f.w, h1, l1);
        int off = r * 256 + ((((c4 >> 3)) ^ (r & 7)) << 4) + (c4 & 7) * 2;
        *(uint2*)(hi + off) = make_uint2(h0, h1);
        *(uint2*)(lo + off) = make_uint2(l0, l1);
    }
}

__global__ __launch_bounds__(THREADS, 1)
void retention_mma_kernel(const float* __restrict__ q, const float* __restrict__ k,
                          const float* __restrict__ v, const float* __restrict__ omask,
                          float* __restrict__ out) {
    extern __shared__ char smc[];
    const uint32_t su = smem_u32(smc);
    const int tid = threadIdx.x;
    const int wid = tid >> 5, lane = tid & 31;
    const int m0 = wid * 32;  // each warp owns rows m0..m0+31, full width
    const int g = lane >> 2;

    const int it = blockIdx.x, h = blockIdx.y, b = blockIdx.z;
    const int i0 = it * BM;
    const size_t bh = (size_t)(b * HEADS + h);
    const float* qbase = q + (bh * S_LEN + i0) * DHEAD;
    const float* kbase = k + bh * S_LEN * DHEAD;
    const float* vbase = v + bh * S_LEN * DHEAD;
    const float* mbase = omask + ((size_t)h * S_LEN + i0) * S_LEN;

    // ---- Q tile [256x128] -> bf16 hi/lo ----
#pragma unroll 4
    for (int x = tid; x < 256 * 32; x += THREADS) {
        int r = x >> 5, c4 = (x & 31) << 2;
        float4 f = *(const float4*)(qbase + r * DHEAD + c4);
        uint32_t h0, l0, h1, l1;
        split2(f.x, f.y, h0, l0);
        split2(f.z, f.w, h1, l1);
        int off = r * 256 + ((((c4 >> 3)) ^ (r & 7)) << 4) + (c4 & 7) * 2;
        *(uint2*)(smc + SM_QHI + off) = make_uint2(h0, h1);
        *(uint2*)(smc + SM_QLO + off) = make_uint2(l0, l1);
    }
    // ---- K/V tile 0 ----
    load_tile(kbase, smc + SM_K, smc + SM_K + 16384, tid);
    load_tile(vbase, smc + SM_V, smc + SM_V + 16384, tid);

    float rn[2][2];
#pragma unroll
    for (int mt = 0; mt < 2; mt++) {
        rn[mt][0] = g_rnorm[h * S_LEN + i0 + m0 + mt * 16 + g];
        rn[mt][1] = g_rnorm[h * S_LEN + i0 + m0 + mt * 16 + g + 8];
    }

    float oacc[2][16][4];
#pragma unroll
    for (int mt = 0; mt < 2; mt++)
#pragma unroll
        for (int nt = 0; nt < 16; nt++)
#pragma unroll
            for (int e = 0; e < 4; e++) oacc[mt][nt][e] = 0.f;

    __syncthreads();

    for (int jt = 0; jt < NJT; jt++) {
        const int buf = jt & 1;
        const bool pf = (jt + 1 < NJT);

        // ---- K prefetch: LDG -> split -> STS into buf^1 (transient regs) ----
        if (pf) {
            char* khn = smc + SM_K + (buf ^ 1) * 32768;
            const float* kbn = kbase + (size_t)(jt + 1) * BN * DHEAD;
            float4 kreg[8];
#pragma unroll
            for (int i = 0; i < 8; i++) {
                int x = tid + i * THREADS;
                kreg[i] = *(const float4*)(kbn + (x >> 5) * DHEAD + ((x & 31) << 2));
            }
#pragma unroll
            for (int i = 0; i < 8; i++) {
                int x = tid + i * THREADS;
                int r = x >> 5, c4 = (x & 31) << 2;
                uint32_t h0, l0, h1, l1;
                split2(kreg[i].x, kreg[i].y, h0, l0);
                split2(kreg[i].z, kreg[i].w, h1, l1);
                int off = r * 256 + ((((c4 >> 3)) ^ (r & 7)) << 4) + (c4 & 7) * 2;
                *(uint2*)(khn + off) = make_uint2(h0, h1);
                *(uint2*)(khn + 16384 + off) = make_uint2(l0, l1);
            }
        }

        // ---- GEMM1: S[m32][j64] = Q @ K^T (bf16x3), B-frags shared across mt ----
        float sacc[2][8][4];
#pragma unroll
        for (int mt = 0; mt < 2; mt++)
#pragma unroll
            for (int nt = 0; nt < 8; nt++)
#pragma unroll
                for (int e = 0; e < 4; e++) sacc[mt][nt][e] = 0.f;

        const uint32_t khb = su + SM_K + buf * 32768, klb = khb + 16384;
        const int krow_b = (lane & 7) + ((lane >> 4) << 3);
#pragma unroll
        for (int ks = 0; ks < 8; ks++) {
            uint32_t qh[2][4], ql[2][4];
#pragma unroll
            for (int mt = 0; mt < 2; mt++) {
                int qrow = m0 + mt * 16 + (lane & 15);
                uint32_t qoff = qrow * 256 + (((2 * ks + (lane >> 4)) ^ (qrow & 7)) << 4);
                ldmx4(qh[mt][0], qh[mt][1], qh[mt][2], qh[mt][3], su + SM_QHI + qoff);
                ldmx4(ql[mt][0], ql[mt][1], ql[mt][2], ql[mt][3], su + SM_QLO + qoff);
            }
#pragma unroll
            for (int np = 0; np < 4; np++) {
                int krow = np * 16 + krow_b;
                uint32_t koff =
                    krow * 256 + (((2 * ks + ((lane >> 3) & 1)) ^ (krow & 7)) << 4);
                uint32_t h0, h1, h2, h3, l0, l1, l2, l3;
                ldmx4(h0, h1, h2, h3, khb + koff);
                ldmx4(l0, l1, l2, l3, klb + koff);
#pragma unroll
                for (int mt = 0; mt < 2; mt++) {
                    mmab(sacc[mt][2 * np], qh[mt], h0, h1);
                    mmab(sacc[mt][2 * np + 1], qh[mt], h2, h3);
                    mmab(sacc[mt][2 * np], qh[mt], l0, l1);
                    mmab(sacc[mt][2 * np + 1], qh[mt], l2, l3);
                    mmab(sacc[mt][2 * np], ql[mt], h0, h1);
                    mmab(sacc[mt][2 * np + 1], ql[mt], h2, h3);
                }
            }
        }

        // ---- V prefetch into regs (held until post-GEMM2 STS) ----
        float4 vreg[8];
        if (pf) {
            const float* vbn = vbase + (size_t)(jt + 1) * BN * DHEAD;
#pragma unroll
            for (int i = 0; i < 8; i++) {
                int x = tid + i * THREADS;
                vreg[i] = *(const float4*)(vbn + (x >> 5) * DHEAD + ((x & 31) << 2));
            }
        }

        // ---- epilogue: sacc *= mask * rn (in place, fp32) ----
#pragma unroll
        for (int mt = 0; mt < 2; mt++) {
            const float* mp =
                mbase + (size_t)(m0 + mt * 16 + g) * S_LEN + jt * BN + (lane & 3) * 2;
#pragma unroll
            for (int nt = 0; nt < 8; nt++) {
                float2 mk0 = *(const float2*)(mp + nt * 8);
                float2 mk1 = *(const float2*)(mp + 8 * S_LEN + nt * 8);
                sacc[mt][nt][0] *= mk0.x * rn[mt][0];
                sacc[mt][nt][1] *= mk0.y * rn[mt][0];
                sacc[mt][nt][2] *= mk1.x * rn[mt][1];
                sacc[mt][nt][3] *= mk1.y * rn[mt][1];
            }
        }

        // ---- GEMM2: O[m32][d128] += S @ V, V-frags shared across mt ----
        const uint32_t vhb = su + SM_V, vlb = vhb + 16384;
#pragma unroll
        for (int kt = 0; kt < 4; kt++) {
            uint32_t ah[2][4], al[2][4];
#pragma unroll
            for (int mt = 0; mt < 2; mt++) {
                split2(sacc[mt][2 * kt][0], sacc[mt][2 * kt][1], ah[mt][0], al[mt][0]);
                split2(sacc[mt][2 * kt][2], sacc[mt][2 * kt][3], ah[mt][1], al[mt][1]);
                split2(sacc[mt][2 * kt + 1][0], sacc[mt][2 * kt + 1][1], ah[mt][2],
                       al[mt][2]);
                split2(sacc[mt][2 * kt + 1][2], sacc[mt][2 * kt + 1][3], ah[mt][3],
                       al[mt][3]);
            }
            const int vrow = kt * 16 + (lane & 15);
#pragma unroll
            for (int np = 0; np < 8; np++) {
                uint32_t voff = vrow * 256 + (((2 * np + (lane >> 4)) ^ (vrow & 7)) << 4);
                uint32_t h0, h1, h2, h3, l0, l1, l2, l3;
                ldmx4t(h0, h1, h2, h3, vhb + voff);
                ldmx4t(l0, l1, l2, l3, vlb + voff);
#pragma unroll
                for (int mt = 0; mt < 2; mt++) {
                    mmab(oacc[mt][2 * np], ah[mt], h0, h1);
                    mmab(oacc[mt][2 * np + 1], ah[mt], h2, h3);
                    mmab(oacc[mt][2 * np], ah[mt], l0, l1);
                    mmab(oacc[mt][2 * np + 1], ah[mt], l2, l3);
                    mmab(oacc[mt][2 * np], al[mt], h0, h1);
                    mmab(oacc[mt][2 * np + 1], al[mt], h2, h3);
                }
            }
        }

        // ---- rotate V buffer ----
        __syncthreads();
        if (pf) {
            char* vh = smc + SM_V;
#pragma unroll
            for (int i = 0; i < 8; i++) {
                int x = tid + i * THREADS;
                int r = x >> 5, c4 = (x & 31) << 2;
                uint32_t h0, l0, h1, l1;
                split2(vreg[i].x, vreg[i].y, h0, l0);
                split2(vreg[i].z, vreg[i].w, h1, l1);
                int off = r * 256 + ((((c4 >> 3)) ^ (r & 7)) << 4) + (c4 & 7) * 2;
                *(uint2*)(vh + off) = make_uint2(h0, h1);
                *(uint2*)(vh + 16384 + off) = make_uint2(l0, l1);
            }
        }
        __syncthreads();
    }

    // ---- RMSNorm (warp-local rows) + store ----
#pragma unroll
    for (int mt = 0; mt < 2; mt++) {
        float p0 = 0.f, p1 = 0.f;
#pragma unroll
        for (int nt = 0; nt < 16; nt++) {
            p0 += oacc[mt][nt][0] * oacc[mt][nt][0] + oacc[mt][nt][1] * oacc[mt][nt][1];
            p1 += oacc[mt][nt][2] * oacc[mt][nt][2] + oacc[mt][nt][3] * oacc[mt][nt][3];
        }
        p0 += __shfl_xor_sync(0xffffffffu, p0, 1);
        p0 += __shfl_xor_sync(0xffffffffu, p0, 2);
        p1 += __shfl_xor_sync(0xffffffffu, p1, 1);
        p1 += __shfl_xor_sync(0xffffffffu, p1, 2);
        float sc0 = rsqrtf(p0 * (1.f / 128.f) + 1e-6f);
        float sc1 = rsqrtf(p1 * (1.f / 128.f) + 1e-6f);
        float* o0 = out + (bh * S_LEN + i0 + m0 + mt * 16 + g) * DHEAD + (lane & 3) * 2;
        float* o1 = o0 + 8 * DHEAD;
#pragma unroll
        for (int nt = 0; nt < 16; nt++) {
            *(float2*)(o0 + nt * 8) = make_float2(oacc[mt][nt][0] * sc0, oacc[mt][nt][1] * sc0);
            *(float2*)(o1 + nt * 8) = make_float2(oacc[mt][nt][2] * sc1, oacc[mt][nt][3] * sc1);
        }
    }
}

extern "C" void kernel_launch(void* const* d_in, const int* in_sizes, int n_in,
                              void* d_out, int out_size) {
    const float* q = (const float*)d_in[0];
    const float* k = (const float*)d_in[1];
    const float* v = (const float*)d_in[2];
    const float* omask = (const float*)d_in[3];
    float* out = (float*)d_out;

    cudaFuncSetAttribute(retention_mma_kernel, cudaFuncAttributeMaxDynamicSharedMemorySize,
                         SMEM_TOTAL);

    rnorm_kernel<<<HEADS * S_LEN, 256>>>(omask);
    retention_mma_kernel<<<dim3(S_LEN / BM, HEADS, BATCH), THREADS, SMEM_TOTAL>>>(
        q, k, v, omask, out);
}